// round 1
// baseline (speedup 1.0000x reference)
#include <cuda_runtime.h>
#include <cstdint>
#include <cstddef>

#define Bc    2
#define Tc    2048
#define Dc    2048
#define Hc    16
#define DKc   128
#define DVc   128
#define KEYD  2048
#define VALD  2048
#define CONVD 6144
#define BT    4096   // B*T

// ---------------- scratch (device globals: allocation-free) ----------------
__device__ float g_mixed[(size_t)BT * CONVD];   // qkv pre-conv
__device__ float g_qkv[(size_t)BT * CONVD];     // post conv+silu (+l2norm in place)
__device__ float g_gb[2 * BT * Hc];             // g then beta
__device__ float g_z[(size_t)BT * VALD];
__device__ float g_od[(size_t)BT * VALD];       // delta-rule output
__device__ float g_y[(size_t)BT * VALD];        // gated-normed, pre out-GEMM

// ---------------- packed f32x2 helpers ----------------
__device__ __forceinline__ unsigned long long pack2(float x, float y) {
    unsigned long long r;
    asm("mov.b64 %0, {%1, %2};" : "=l"(r) : "f"(x), "f"(y));
    return r;
}
__device__ __forceinline__ void unpack2(unsigned long long c, float& lo, float& hi) {
    asm("mov.b64 {%0, %1}, %2;" : "=f"(lo), "=f"(hi) : "l"(c));
}
__device__ __forceinline__ void ffma2(unsigned long long& c, unsigned long long a,
                                      unsigned long long b) {
    asm("fma.rn.f32x2 %0, %1, %2, %0;" : "+l"(c) : "l"(a), "l"(b));
}

// ---------------- SGEMM: C[M,N] = A[M,K] @ B[K,N], all row-major ----------------
// BM=BN=128, BK=16, 256 threads, 8x8 microtile, f32x2 packed accumulation
// (pairs along M). Requires M%128==0, N%128==0, K%16==0 (true for all our shapes).
#define BMg 128
#define BNg 128
#define BKg 16

__global__ __launch_bounds__(256, 2)
void sgemm_kernel(const float* __restrict__ A, const float* __restrict__ B,
                  float* __restrict__ C, int M, int N, int Kd) {
    __shared__ float As[BKg][BMg];
    __shared__ float Bs[BKg][BNg];

    const int tid = threadIdx.x;
    const int bx = blockIdx.x;   // N tile
    const int by = blockIdx.y;   // M tile
    const int tx = tid & 15;     // col group
    const int ty = tid >> 4;     // row group

    const int aRow = tid >> 1;          // 0..127
    const int aCol = (tid & 1) * 8;     // 0 or 8
    const int bRow = tid >> 4;          // 0..15
    const int bCol = (tid & 15) * 8;    // 0..120

    const float* Ag = A + (size_t)(by * BMg + aRow) * Kd + aCol;
    const float* Bg = B + (size_t)bRow * N + bx * BNg + bCol;

    unsigned long long acc[4][8];
#pragma unroll
    for (int i = 0; i < 4; ++i)
#pragma unroll
        for (int j = 0; j < 8; ++j) acc[i][j] = 0ull;

    const int ktiles = Kd / BKg;
    for (int kt = 0; kt < ktiles; ++kt) {
        float4 a0 = *(const float4*)(Ag);
        float4 a1 = *(const float4*)(Ag + 4);
        float4 b0 = *(const float4*)(Bg);
        float4 b1 = *(const float4*)(Bg + 4);
        __syncthreads();
        As[aCol + 0][aRow] = a0.x; As[aCol + 1][aRow] = a0.y;
        As[aCol + 2][aRow] = a0.z; As[aCol + 3][aRow] = a0.w;
        As[aCol + 4][aRow] = a1.x; As[aCol + 5][aRow] = a1.y;
        As[aCol + 6][aRow] = a1.z; As[aCol + 7][aRow] = a1.w;
        *(float4*)&Bs[bRow][bCol]     = b0;
        *(float4*)&Bs[bRow][bCol + 4] = b1;
        __syncthreads();

#pragma unroll
        for (int kk = 0; kk < BKg; ++kk) {
            float4 av0 = *(const float4*)&As[kk][ty * 8];
            float4 av1 = *(const float4*)&As[kk][ty * 8 + 4];
            unsigned long long ap[4];
            ap[0] = pack2(av0.x, av0.y); ap[1] = pack2(av0.z, av0.w);
            ap[2] = pack2(av1.x, av1.y); ap[3] = pack2(av1.z, av1.w);
            float4 bv0 = *(const float4*)&Bs[kk][tx * 8];
            float4 bv1 = *(const float4*)&Bs[kk][tx * 8 + 4];
            float bv[8] = {bv0.x, bv0.y, bv0.z, bv0.w, bv1.x, bv1.y, bv1.z, bv1.w};
#pragma unroll
            for (int j = 0; j < 8; ++j) {
                unsigned long long bd = pack2(bv[j], bv[j]);
#pragma unroll
                for (int i = 0; i < 4; ++i) ffma2(acc[i][j], ap[i], bd);
            }
        }
        Ag += BKg;
        Bg += (size_t)BKg * N;
    }

    // epilogue
    float* Cp = C + (size_t)(by * BMg + ty * 8) * N + bx * BNg + tx * 8;
#pragma unroll
    for (int i2 = 0; i2 < 4; ++i2) {
        float lo[8], hi[8];
#pragma unroll
        for (int j = 0; j < 8; ++j) unpack2(acc[i2][j], lo[j], hi[j]);
        float* r0 = Cp + (size_t)(2 * i2) * N;
        float* r1 = r0 + N;
        *(float4*)(r0)     = make_float4(lo[0], lo[1], lo[2], lo[3]);
        *(float4*)(r0 + 4) = make_float4(lo[4], lo[5], lo[6], lo[7]);
        *(float4*)(r1)     = make_float4(hi[0], hi[1], hi[2], hi[3]);
        *(float4*)(r1 + 4) = make_float4(hi[4], hi[5], hi[6], hi[7]);
    }
}

// ---------------- depthwise causal conv (K=4) + silu ----------------
__global__ void conv_silu_kernel(const float* __restrict__ mixed,
                                 const float* __restrict__ cw,
                                 float* __restrict__ out) {
    const int c  = blockIdx.x * 128 + threadIdx.x;
    const int b  = blockIdx.z;
    const int t0 = blockIdx.y * 256;
    const float w0 = cw[c * 4 + 0], w1 = cw[c * 4 + 1];
    const float w2 = cw[c * 4 + 2], w3 = cw[c * 4 + 3];
    const float* base  = mixed + (size_t)b * Tc * CONVD + c;
    float*       obase = out   + (size_t)b * Tc * CONVD + c;
    float xm3 = (t0 >= 3) ? base[(size_t)(t0 - 3) * CONVD] : 0.f;
    float xm2 = (t0 >= 2) ? base[(size_t)(t0 - 2) * CONVD] : 0.f;
    float xm1 = (t0 >= 1) ? base[(size_t)(t0 - 1) * CONVD] : 0.f;
    for (int t = t0; t < t0 + 256; ++t) {
        float x = base[(size_t)t * CONVD];
        float y = w0 * xm3 + w1 * xm2 + w2 * xm1 + w3 * x;
        float s = 1.f / (1.f + expf(-y));
        obase[(size_t)t * CONVD] = y * s;
        xm3 = xm2; xm2 = xm1; xm1 = x;
    }
}

// ---------------- per-head L2 norm for q and k (in place) ----------------
__global__ void l2norm_kernel(float* __restrict__ qkv) {
    const int warp = threadIdx.x >> 5, lane = threadIdx.x & 31;
    const int vec = blockIdx.x * 8 + warp;      // [0, 2*BT*H)
    const int qk = vec >> 16;                   // BT*H == 65536
    const int r  = vec & 65535;
    const int bt = r >> 4, h = r & 15;
    float* p = qkv + (size_t)bt * CONVD + qk * KEYD + h * 128 + lane * 4;
    float4 v = *(float4*)p;
    float ss = v.x * v.x + v.y * v.y + v.z * v.z + v.w * v.w;
#pragma unroll
    for (int off = 16; off; off >>= 1) ss += __shfl_xor_sync(~0u, ss, off);
    float scale = rsqrtf(ss + 1e-6f);
    if (qk == 0) scale *= 0.08838834764831845f;   // DK^-0.5
    v.x *= scale; v.y *= scale; v.z *= scale; v.w *= scale;
    *(float4*)p = v;
}

// ---------------- g and beta projections ----------------
__global__ __launch_bounds__(256)
void proj_ab_kernel(const float* __restrict__ hs, const float* __restrict__ Wb,
                    const float* __restrict__ Wa, const float* __restrict__ dt_bias,
                    const float* __restrict__ A_log, float* __restrict__ gb) {
    __shared__ float row[Dc];
    const int m = blockIdx.x;
    const float* hr = hs + (size_t)m * Dc;
    {
        int i = threadIdx.x * 8;
        *(float4*)&row[i]     = *(const float4*)&hr[i];
        *(float4*)&row[i + 4] = *(const float4*)&hr[i + 4];
    }
    __syncthreads();
    const int warp = threadIdx.x >> 5, lane = threadIdx.x & 31;
#pragma unroll
    for (int oo = 0; oo < 4; ++oo) {
        int idx = warp * 4 + oo;              // 0..31
        const float* W = (idx < 16) ? Wa : Wb;
        int h = idx & 15;
        float s = 0.f;
        for (int kk = lane; kk < Dc; kk += 32) s += row[kk] * W[kk * Hc + h];
#pragma unroll
        for (int off = 16; off; off >>= 1) s += __shfl_xor_sync(~0u, s, off);
        if (lane == 0) {
            if (idx < 16) {
                float x = s + dt_bias[h];
                float sp = (x > 20.f) ? x : log1pf(expf(x));
                gb[(size_t)m * Hc + h] = -expf(A_log[h]) * sp;
            } else {
                gb[(size_t)BT * Hc + (size_t)m * Hc + h] = 1.f / (1.f + expf(-s));
            }
        }
    }
}

// ---------------- gated delta rule scan ----------------
// grid: B*H*4 blocks (4 v-blocks of 32); 256 threads; tk in [0,16) owns 8 k's,
// tv in [0,16) owns 2 v's. State slice 128x32 lives in registers (16 f/thread).
__global__ __launch_bounds__(256, 1)
void scan_kernel(const float* __restrict__ qkv, const float* __restrict__ gb,
                 float* __restrict__ od) {
    const int blk  = blockIdx.x;
    const int vblk = blk & 3;
    const int h    = (blk >> 2) & 15;
    const int b    = blk >> 6;
    const int tid = threadIdx.x;
    const int tk = tid & 15, tv = tid >> 4;
    const int vbase = vblk * 32 + tv * 2;

    const float* qp = qkv + (size_t)b * Tc * CONVD + h * 128 + tk * 8;
    const float* kp = qp + KEYD;
    const float* vp = qkv + (size_t)b * Tc * CONVD + 2 * KEYD + h * 128 + vbase;
    const float* gp = gb + (size_t)b * Tc * Hc + h;
    const float* bp = gp + (size_t)BT * Hc;
    float* op = od + ((size_t)b * Tc * Hc + h) * 128 + vbase;

    float S[8][2];
#pragma unroll
    for (int i = 0; i < 8; ++i) { S[i][0] = 0.f; S[i][1] = 0.f; }

    for (int t = 0; t < Tc; ++t) {
        float4 q0 = *(const float4*)qp, q1 = *(const float4*)(qp + 4);
        float4 k0 = *(const float4*)kp, k1 = *(const float4*)(kp + 4);
        float2 vv = *(const float2*)vp;
        float gg = *gp, bb = *bp;
        float eg = __expf(gg);
        float kr[8] = {k0.x, k0.y, k0.z, k0.w, k1.x, k1.y, k1.z, k1.w};
        float qr[8] = {q0.x, q0.y, q0.z, q0.w, q1.x, q1.y, q1.z, q1.w};

        float kv0 = 0.f, kv1 = 0.f;
#pragma unroll
        for (int i = 0; i < 8; ++i) {
            S[i][0] *= eg; S[i][1] *= eg;
            kv0 += kr[i] * S[i][0];
            kv1 += kr[i] * S[i][1];
        }
#pragma unroll
        for (int off = 8; off; off >>= 1) {
            kv0 += __shfl_xor_sync(~0u, kv0, off);
            kv1 += __shfl_xor_sync(~0u, kv1, off);
        }
        float d0 = (vv.x - kv0) * bb;
        float d1 = (vv.y - kv1) * bb;
        float o0 = 0.f, o1 = 0.f;
#pragma unroll
        for (int i = 0; i < 8; ++i) {
            S[i][0] += kr[i] * d0; S[i][1] += kr[i] * d1;
            o0 += qr[i] * S[i][0];
            o1 += qr[i] * S[i][1];
        }
#pragma unroll
        for (int off = 8; off; off >>= 1) {
            o0 += __shfl_xor_sync(~0u, o0, off);
            o1 += __shfl_xor_sync(~0u, o1, off);
        }
        if (tk == 0) {
            float2 ov; ov.x = o0; ov.y = o1;
            *(float2*)op = ov;
        }
        qp += CONVD; kp += CONVD; vp += CONVD;
        gp += Hc; bp += Hc;
        op += (size_t)Hc * 128;
    }
}

// ---------------- gated RMSNorm ----------------
__global__ void gate_norm_kernel(const float* __restrict__ od,
                                 const float* __restrict__ z,
                                 const float* __restrict__ nw,
                                 float* __restrict__ y) {
    const int warp = threadIdx.x >> 5, lane = threadIdx.x & 31;
    const int vec = blockIdx.x * 8 + warp;      // bt*H + h
    const float* opv = od + (size_t)vec * 128 + lane * 4;
    const float* zpv = z  + (size_t)vec * 128 + lane * 4;
    float4 o  = *(const float4*)opv;
    float4 zz = *(const float4*)zpv;
    float4 og;
    og.x = o.x * (zz.x / (1.f + expf(-zz.x)));
    og.y = o.y * (zz.y / (1.f + expf(-zz.y)));
    og.z = o.z * (zz.z / (1.f + expf(-zz.z)));
    og.w = o.w * (zz.w / (1.f + expf(-zz.w)));
    float ss = og.x * og.x + og.y * og.y + og.z * og.z + og.w * og.w;
#pragma unroll
    for (int off = 16; off; off >>= 1) ss += __shfl_xor_sync(~0u, ss, off);
    float r = rsqrtf(ss * (1.f / 128.f) + 1e-6f);
    float4 w = *(const float4*)&nw[lane * 4];
    float4 out;
    out.x = og.x * r * w.x; out.y = og.y * r * w.y;
    out.z = og.z * r * w.z; out.w = og.w * r * w.w;
    *(float4*)(y + (size_t)vec * 128 + lane * 4) = out;
}

// ---------------- launch ----------------
extern "C" void kernel_launch(void* const* d_in, const int* in_sizes, int n_in,
                              void* d_out, int out_size) {
    const float* hs      = (const float*)d_in[0];
    const float* W_qkv   = (const float*)d_in[1];
    const float* conv_w  = (const float*)d_in[2];
    const float* W_z     = (const float*)d_in[3];
    const float* W_b     = (const float*)d_in[4];
    const float* W_a     = (const float*)d_in[5];
    const float* dt_bias = (const float*)d_in[6];
    const float* A_log   = (const float*)d_in[7];
    const float* norm_w  = (const float*)d_in[8];
    const float* W_out   = (const float*)d_in[9];
    float* out = (float*)d_out;

    float *mixed, *qkv, *gb, *z, *od, *y;
    cudaGetSymbolAddress((void**)&mixed, g_mixed);
    cudaGetSymbolAddress((void**)&qkv,   g_qkv);
    cudaGetSymbolAddress((void**)&gb,    g_gb);
    cudaGetSymbolAddress((void**)&z,     g_z);
    cudaGetSymbolAddress((void**)&od,    g_od);
    cudaGetSymbolAddress((void**)&y,     g_y);

    // 1. mixed = hs @ W_qkv   [4096, 6144]
    sgemm_kernel<<<dim3(CONVD / BNg, BT / BMg), 256>>>(hs, W_qkv, mixed, BT, CONVD, Dc);
    // 2. depthwise causal conv + silu
    conv_silu_kernel<<<dim3(CONVD / 128, Tc / 256, Bc), 128>>>(mixed, conv_w, qkv);
    // 3. l2norm q, k (in place)
    l2norm_kernel<<<(2 * BT * Hc) / 8, 256>>>(qkv);
    // 4. g, beta
    proj_ab_kernel<<<BT, 256>>>(hs, W_b, W_a, dt_bias, A_log, gb);
    // 5. z = hs @ W_z
    sgemm_kernel<<<dim3(VALD / BNg, BT / BMg), 256>>>(hs, W_z, z, BT, VALD, Dc);
    // 6. gated delta rule scan
    scan_kernel<<<Bc * Hc * 4, 256>>>(qkv, gb, od);
    // 7. gated RMSNorm
    gate_norm_kernel<<<(BT * Hc) / 8, 256>>>(od, z, norm_w, y);
    // 8. out = y @ W_out
    sgemm_kernel<<<dim3(Dc / BNg, BT / BMg), 256>>>(y, W_out, out, BT, Dc, Dc);
}

// round 3
// speedup vs baseline: 1.3608x; 1.3608x over previous
#include <cuda_runtime.h>
#include <cuda_bf16.h>
#include <cstdint>
#include <cstddef>

#define Bc    2
#define Tc    2048
#define Dc    2048
#define Hc    16
#define KEYD  2048
#define VALD  2048
#define CONVD 6144
#define BT    4096   // B*T

typedef unsigned short u16;
typedef uint32_t u32;

// ---------------- scratch (device globals: allocation-free) ----------------
__device__ float g_mixed[(size_t)BT * CONVD];   // qkv pre-conv (fp32)
__device__ float g_qkv[(size_t)BT * CONVD];     // post conv+silu (+l2norm in place)
__device__ float g_gb[2 * BT * Hc];             // g then beta
__device__ float g_z[(size_t)BT * VALD];
__device__ float g_od[(size_t)BT * VALD];       // delta-rule output
__device__ float g_Cab[(size_t)BT * 32];        // a/b projection pre-activation

// bf16 hi/lo operands
__device__ u16 g_hsA_hi[(size_t)BT * Dc];
__device__ u16 g_hsA_lo[(size_t)BT * Dc];
__device__ u16 g_Wq_hi[(size_t)CONVD * Dc];
__device__ u16 g_Wq_lo[(size_t)CONVD * Dc];
__device__ u16 g_Wz_hi[(size_t)VALD * Dc];
__device__ u16 g_Wz_lo[(size_t)VALD * Dc];
__device__ u16 g_Wo_hi[(size_t)Dc * VALD];
__device__ u16 g_Wo_lo[(size_t)Dc * VALD];
__device__ u16 g_ab_hi[(size_t)32 * Dc];
__device__ u16 g_ab_lo[(size_t)32 * Dc];
__device__ u16 g_y_hi[(size_t)BT * VALD];
__device__ u16 g_y_lo[(size_t)BT * VALD];

// ---------------- helpers ----------------
__device__ __forceinline__ u16 bf16bits(float x) {
    __nv_bfloat16 b = __float2bfloat16(x);
    return *reinterpret_cast<u16*>(&b);
}
__device__ __forceinline__ float bf16val(u16 u) {
    __nv_bfloat16 b;
    *reinterpret_cast<u16*>(&b) = u;
    return __bfloat162float(b);
}
__device__ __forceinline__ u32 smem_u32(const void* p) {
    u32 a;
    asm("{ .reg .u64 t; cvta.to.shared.u64 t, %1; cvt.u32.u64 %0, t; }" : "=r"(a) : "l"(p));
    return a;
}
#define SWZ(x) ((x) ^ (((x) >> 3) & 0x70))

__device__ __forceinline__ void cp16(u32 s, const void* g) {
    asm volatile("cp.async.cg.shared.global [%0], [%1], 16;" :: "r"(s), "l"(g));
}
__device__ __forceinline__ void ldsm4(u32* r, u32 a) {
    asm volatile("ldmatrix.sync.aligned.m8n8.x4.shared.b16 {%0,%1,%2,%3}, [%4];"
                 : "=r"(r[0]), "=r"(r[1]), "=r"(r[2]), "=r"(r[3]) : "r"(a));
}
__device__ __forceinline__ void mma16816(float* c, const u32* a, const u32* b) {
    asm volatile(
        "mma.sync.aligned.m16n8k16.row.col.f32.bf16.bf16.f32 "
        "{%0,%1,%2,%3}, {%4,%5,%6,%7}, {%8,%9}, {%0,%1,%2,%3};"
        : "+f"(c[0]), "+f"(c[1]), "+f"(c[2]), "+f"(c[3])
        : "r"(a[0]), "r"(a[1]), "r"(a[2]), "r"(a[3]), "r"(b[0]), "r"(b[1]));
}

// ---------------- operand conversion kernels ----------------
__global__ void cvt_hilo_kernel(const float4* __restrict__ in,
                                ushort4* __restrict__ hi, ushort4* __restrict__ lo,
                                int n4) {
    int i = blockIdx.x * 256 + threadIdx.x;
    if (i >= n4) return;
    float4 v = in[i];
    ushort4 H, L;
    H.x = bf16bits(v.x); L.x = bf16bits(v.x - bf16val(H.x));
    H.y = bf16bits(v.y); L.y = bf16bits(v.y - bf16val(H.y));
    H.z = bf16bits(v.z); L.z = bf16bits(v.z - bf16val(H.z));
    H.w = bf16bits(v.w); L.w = bf16bits(v.w - bf16val(H.w));
    hi[i] = H; lo[i] = L;
}

// transpose + hi/lo convert: W [Kd, N] fp32 -> T [N, Kd] bf16
__global__ void transpose_cvt_kernel(const float* __restrict__ W,
                                     u16* __restrict__ Thi, u16* __restrict__ Tlo,
                                     int Kd, int N) {
    __shared__ float t[32][33];
    int n0 = blockIdx.x * 32, k0 = blockIdx.y * 32;
    int x = threadIdx.x, y = threadIdx.y;   // 32 x 8
#pragma unroll
    for (int i = 0; i < 4; ++i)
        t[y + 8 * i][x] = W[(size_t)(k0 + y + 8 * i) * N + n0 + x];
    __syncthreads();
#pragma unroll
    for (int i = 0; i < 4; ++i) {
        float v = t[x][y + 8 * i];
        u16 h = bf16bits(v);
        size_t o = (size_t)(n0 + y + 8 * i) * Kd + k0 + x;
        Thi[o] = h;
        Tlo[o] = bf16bits(v - bf16val(h));
    }
}

// Wa,Wb [D,16] -> [32, D] bf16 (rows 0-15 = Wa^T, 16-31 = Wb^T)
__global__ void transpose_ab_kernel(const float* __restrict__ Wa,
                                    const float* __restrict__ Wb,
                                    u16* __restrict__ hi, u16* __restrict__ lo) {
    int n = blockIdx.y;
    int k = blockIdx.x * 256 + threadIdx.x;
    const float* W = (n < 16) ? Wa : Wb;
    float v = W[(size_t)k * Hc + (n & 15)];
    u16 h = bf16bits(v);
    hi[(size_t)n * Dc + k] = h;
    lo[(size_t)n * Dc + k] = bf16bits(v - bf16val(h));
}

// ---------------- HMMA GEMM: C[M,N] = A[M,K] @ Bt[N,K]^T ----------------
// bf16 hi/lo split (3 products) with fp32 accumulate.
// 256 threads = 8 warps (4 m x 2 n). BK=64. 3-stage cp.async pipeline.
template <int BN>
__global__ __launch_bounds__(256, 1)
void mma_gemm(const u16* __restrict__ Ahi, const u16* __restrict__ Alo,
              const u16* __restrict__ Bhi, const u16* __restrict__ Blo,
              float* __restrict__ C, int M, int N, int Kd) {
    extern __shared__ __align__(1024) char smem[];
    constexpr int ATILE = 128 * 128;          // bytes per A tile (128 rows x 128B)
    constexpr int BTILE = BN * 128;
    constexpr int STAGE = 2 * ATILE + 2 * BTILE;
    constexpr int WN = BN / 2;                // warp n-tile
    constexpr int NG = WN / 16;               // ldmatrix.x4 groups per k16
    const int tid = threadIdx.x, lane = tid & 31, wid = tid >> 5;
    const int wm = (wid & 3) * 32;
    const int wn = (wid >> 2) * WN;
    const int m0 = blockIdx.y * 128, n0 = blockIdx.x * BN;
    const int ktiles = Kd >> 6;
    const u32 sb = smem_u32(smem);

    const u16* srcs[4] = {Ahi + (size_t)m0 * Kd, Alo + (size_t)m0 * Kd,
                          Bhi + (size_t)n0 * Kd, Blo + (size_t)n0 * Kd};
    const int rows[4] = {128, 128, BN, BN};
    const u32 offs[4] = {0, ATILE, 2 * ATILE, 2 * ATILE + (u32)BTILE};

    auto issue = [&](int kt) {
        const int ko = kt << 6;
        const u32 st = sb + (u32)(kt % 3) * STAGE;
#pragma unroll
        for (int r = 0; r < 4; ++r) {
            for (int c = tid; c < rows[r] * 8; c += 256) {
                int rr = c >> 3, u = c & 7;
                cp16(st + offs[r] + SWZ(rr * 128 + u * 16),
                     srcs[r] + (size_t)rr * Kd + ko + u * 8);
            }
        }
    };

    float acc[2][WN / 8][4];
#pragma unroll
    for (int i = 0; i < 2; ++i)
#pragma unroll
        for (int j = 0; j < WN / 8; ++j)
#pragma unroll
            for (int l = 0; l < 4; ++l) acc[i][j][l] = 0.f;

    issue(0);
    asm volatile("cp.async.commit_group;");
    if (ktiles > 1) issue(1);
    asm volatile("cp.async.commit_group;");

    for (int kt = 0; kt < ktiles; ++kt) {
        if (kt + 2 < ktiles) issue(kt + 2);
        asm volatile("cp.async.commit_group;");
        asm volatile("cp.async.wait_group 2;" ::: "memory");
        __syncthreads();
        const u32 Ab = sb + (u32)(kt % 3) * STAGE;
        const u32 Bb = Ab + 2 * ATILE;
#pragma unroll
        for (int ks = 0; ks < 4; ++ks) {
            u32 ah[2][4], al[2][4], bh[NG][4], bl[NG][4];
            const int arow = wm + (lane & 15);
            const int acol = ks * 32 + ((lane >> 4) << 4);
#pragma unroll
            for (int mf = 0; mf < 2; ++mf) {
                u32 ad = Ab + SWZ((arow + mf * 16) * 128 + acol);
                ldsm4(ah[mf], ad);
                ldsm4(al[mf], ad + ATILE);
            }
            const int brow = wn + (lane & 7) + ((lane >> 4) << 3);
            const int bcol = ks * 32 + ((lane & 8) << 1);
#pragma unroll
            for (int g = 0; g < NG; ++g) {
                u32 bd = Bb + SWZ((brow + g * 16) * 128 + bcol);
                ldsm4(bh[g], bd);
                ldsm4(bl[g], bd + BTILE);
            }
#pragma unroll
            for (int mf = 0; mf < 2; ++mf)
#pragma unroll
                for (int g = 0; g < NG; ++g) {
                    mma16816(acc[mf][2 * g + 0], ah[mf], &bh[g][0]);
                    mma16816(acc[mf][2 * g + 1], ah[mf], &bh[g][2]);
                    mma16816(acc[mf][2 * g + 0], ah[mf], &bl[g][0]);
                    mma16816(acc[mf][2 * g + 1], ah[mf], &bl[g][2]);
                    mma16816(acc[mf][2 * g + 0], al[mf], &bh[g][0]);
                    mma16816(acc[mf][2 * g + 1], al[mf], &bh[g][2]);
                }
        }
        __syncthreads();
    }

    // epilogue: direct gmem stores
#pragma unroll
    for (int mf = 0; mf < 2; ++mf)
#pragma unroll
        for (int f = 0; f < WN / 8; ++f) {
            int row = m0 + wm + mf * 16 + (lane >> 2);
            int col = n0 + wn + f * 8 + (lane & 3) * 2;
            float2 lo2, hi2;
            lo2.x = acc[mf][f][0]; lo2.y = acc[mf][f][1];
            hi2.x = acc[mf][f][2]; hi2.y = acc[mf][f][3];
            *(float2*)&C[(size_t)row * N + col] = lo2;
            *(float2*)&C[(size_t)(row + 8) * N + col] = hi2;
        }
}

// ---------------- depthwise causal conv (K=4) + silu ----------------
__global__ void conv_silu_kernel(const float* __restrict__ mixed,
                                 const float* __restrict__ cw,
                                 float* __restrict__ out) {
    const int c  = blockIdx.x * 128 + threadIdx.x;
    const int b  = blockIdx.z;
    const int t0 = blockIdx.y * 256;
    const float w0 = cw[c * 4 + 0], w1 = cw[c * 4 + 1];
    const float w2 = cw[c * 4 + 2], w3 = cw[c * 4 + 3];
    const float* base  = mixed + (size_t)b * Tc * CONVD + c;
    float*       obase = out   + (size_t)b * Tc * CONVD + c;
    float xm3 = (t0 >= 3) ? base[(size_t)(t0 - 3) * CONVD] : 0.f;
    float xm2 = (t0 >= 2) ? base[(size_t)(t0 - 2) * CONVD] : 0.f;
    float xm1 = (t0 >= 1) ? base[(size_t)(t0 - 1) * CONVD] : 0.f;
    for (int t = t0; t < t0 + 256; ++t) {
        float x = base[(size_t)t * CONVD];
        float y = w0 * xm3 + w1 * xm2 + w2 * xm1 + w3 * x;
        float s = 1.f / (1.f + expf(-y));
        obase[(size_t)t * CONVD] = y * s;
        xm3 = xm2; xm2 = xm1; xm1 = x;
    }
}

// ---------------- per-head L2 norm for q and k (in place) ----------------
__global__ void l2norm_kernel(float* __restrict__ qkv) {
    const int warp = threadIdx.x >> 5, lane = threadIdx.x & 31;
    const int vec = blockIdx.x * 8 + warp;      // [0, 2*BT*H)
    const int qk = vec >> 16;                   // BT*H == 65536
    const int r  = vec & 65535;
    const int bt = r >> 4, h = r & 15;
    float* p = qkv + (size_t)bt * CONVD + qk * KEYD + h * 128 + lane * 4;
    float4 v = *(float4*)p;
    float ss = v.x * v.x + v.y * v.y + v.z * v.z + v.w * v.w;
#pragma unroll
    for (int off = 16; off; off >>= 1) ss += __shfl_xor_sync(~0u, ss, off);
    float scale = rsqrtf(ss + 1e-6f);
    if (qk == 0) scale *= 0.08838834764831845f;   // DK^-0.5
    v.x *= scale; v.y *= scale; v.z *= scale; v.w *= scale;
    *(float4*)p = v;
}

// ---------------- a/b activation ----------------
__global__ void ab_act_kernel(const float* __restrict__ Cab,
                              const float* __restrict__ dt_bias,
                              const float* __restrict__ A_log,
                              float* __restrict__ gb) {
    int i = blockIdx.x * 256 + threadIdx.x;     // over BT*16
    int m = i >> 4, h = i & 15;
    float av = Cab[(size_t)m * 32 + h];
    float bv = Cab[(size_t)m * 32 + 16 + h];
    float x = av + dt_bias[h];
    float sp = (x > 20.f) ? x : log1pf(expf(x));
    gb[i] = -expf(A_log[h]) * sp;
    gb[(size_t)BT * Hc + i] = 1.f / (1.f + expf(-bv));
}

// ---------------- gated delta rule scan ----------------
__global__ __launch_bounds__(256, 1)
void scan_kernel(const float* __restrict__ qkv, const float* __restrict__ gb,
                 float* __restrict__ od) {
    const int blk  = blockIdx.x;
    const int vblk = blk & 3;
    const int h    = (blk >> 2) & 15;
    const int b    = blk >> 6;
    const int tid = threadIdx.x;
    const int tk = tid & 15, tv = tid >> 4;
    const int vbase = vblk * 32 + tv * 2;

    const float* qp = qkv + (size_t)b * Tc * CONVD + h * 128 + tk * 8;
    const float* kp = qp + KEYD;
    const float* vp = qkv + (size_t)b * Tc * CONVD + 2 * KEYD + h * 128 + vbase;
    const float* gp = gb + (size_t)b * Tc * Hc + h;
    const float* bp = gp + (size_t)BT * Hc;
    float* op = od + ((size_t)b * Tc * Hc + h) * 128 + vbase;

    float S[8][2];
#pragma unroll
    for (int i = 0; i < 8; ++i) { S[i][0] = 0.f; S[i][1] = 0.f; }

    for (int t = 0; t < Tc; ++t) {
        float4 q0 = *(const float4*)qp, q1 = *(const float4*)(qp + 4);
        float4 k0 = *(const float4*)kp, k1 = *(const float4*)(kp + 4);
        float2 vv = *(const float2*)vp;
        float gg = *gp, bb = *bp;
        float eg = __expf(gg);
        float kr[8] = {k0.x, k0.y, k0.z, k0.w, k1.x, k1.y, k1.z, k1.w};
        float qr[8] = {q0.x, q0.y, q0.z, q0.w, q1.x, q1.y, q1.z, q1.w};

        float kv0 = 0.f, kv1 = 0.f;
#pragma unroll
        for (int i = 0; i < 8; ++i) {
            S[i][0] *= eg; S[i][1] *= eg;
            kv0 += kr[i] * S[i][0];
            kv1 += kr[i] * S[i][1];
        }
#pragma unroll
        for (int off = 8; off; off >>= 1) {
            kv0 += __shfl_xor_sync(~0u, kv0, off);
            kv1 += __shfl_xor_sync(~0u, kv1, off);
        }
        float d0 = (vv.x - kv0) * bb;
        float d1 = (vv.y - kv1) * bb;
        float o0 = 0.f, o1 = 0.f;
#pragma unroll
        for (int i = 0; i < 8; ++i) {
            S[i][0] += kr[i] * d0; S[i][1] += kr[i] * d1;
            o0 += qr[i] * S[i][0];
            o1 += qr[i] * S[i][1];
        }
#pragma unroll
        for (int off = 8; off; off >>= 1) {
            o0 += __shfl_xor_sync(~0u, o0, off);
            o1 += __shfl_xor_sync(~0u, o1, off);
        }
        if (tk == 0) {
            float2 ov; ov.x = o0; ov.y = o1;
            *(float2*)op = ov;
        }
        qp += CONVD; kp += CONVD; vp += CONVD;
        gp += Hc; bp += Hc;
        op += (size_t)Hc * 128;
    }
}

// ---------------- gated RMSNorm -> bf16 hi/lo ----------------
__global__ void gate_norm_kernel(const float* __restrict__ od,
                                 const float* __restrict__ z,
                                 const float* __restrict__ nw,
                                 ushort4* __restrict__ yhi,
                                 ushort4* __restrict__ ylo) {
    const int warp = threadIdx.x >> 5, lane = threadIdx.x & 31;
    const int vec = blockIdx.x * 8 + warp;      // bt*H + h
    const float* opv = od + (size_t)vec * 128 + lane * 4;
    const float* zpv = z  + (size_t)vec * 128 + lane * 4;
    float4 o  = *(const float4*)opv;
    float4 zz = *(const float4*)zpv;
    float4 og;
    og.x = o.x * (zz.x / (1.f + expf(-zz.x)));
    og.y = o.y * (zz.y / (1.f + expf(-zz.y)));
    og.z = o.z * (zz.z / (1.f + expf(-zz.z)));
    og.w = o.w * (zz.w / (1.f + expf(-zz.w)));
    float ss = og.x * og.x + og.y * og.y + og.z * og.z + og.w * og.w;
#pragma unroll
    for (int off = 16; off; off >>= 1) ss += __shfl_xor_sync(~0u, ss, off);
    float r = rsqrtf(ss * (1.f / 128.f) + 1e-6f);
    float4 w = *(const float4*)&nw[lane * 4];
    float4 out;
    out.x = og.x * r * w.x; out.y = og.y * r * w.y;
    out.z = og.z * r * w.z; out.w = og.w * r * w.w;
    ushort4 H, L;
    H.x = bf16bits(out.x); L.x = bf16bits(out.x - bf16val(H.x));
    H.y = bf16bits(out.y); L.y = bf16bits(out.y - bf16val(H.y));
    H.z = bf16bits(out.z); L.z = bf16bits(out.z - bf16val(H.z));
    H.w = bf16bits(out.w); L.w = bf16bits(out.w - bf16val(H.w));
    yhi[(size_t)vec * 32 + lane] = H;
    ylo[(size_t)vec * 32 + lane] = L;
}

// ---------------- launch ----------------
extern "C" void kernel_launch(void* const* d_in, const int* in_sizes, int n_in,
                              void* d_out, int out_size) {
    const float* hs      = (const float*)d_in[0];
    const float* W_qkv   = (const float*)d_in[1];
    const float* conv_w  = (const float*)d_in[2];
    const float* W_z     = (const float*)d_in[3];
    const float* W_b     = (const float*)d_in[4];
    const float* W_a     = (const float*)d_in[5];
    const float* dt_bias = (const float*)d_in[6];
    const float* A_log   = (const float*)d_in[7];
    const float* norm_w  = (const float*)d_in[8];
    const float* W_out   = (const float*)d_in[9];
    float* out = (float*)d_out;

    float *mixed, *qkv, *gb, *z, *od, *Cab;
    u16 *hsA_hi, *hsA_lo, *Wq_hi, *Wq_lo, *Wz_hi, *Wz_lo;
    u16 *Wo_hi, *Wo_lo, *ab_hi, *ab_lo, *y_hi, *y_lo;
    cudaGetSymbolAddress((void**)&mixed, g_mixed);
    cudaGetSymbolAddress((void**)&qkv,   g_qkv);
    cudaGetSymbolAddress((void**)&gb,    g_gb);
    cudaGetSymbolAddress((void**)&z,     g_z);
    cudaGetSymbolAddress((void**)&od,    g_od);
    cudaGetSymbolAddress((void**)&Cab,   g_Cab);
    cudaGetSymbolAddress((void**)&hsA_hi, g_hsA_hi);
    cudaGetSymbolAddress((void**)&hsA_lo, g_hsA_lo);
    cudaGetSymbolAddress((void**)&Wq_hi,  g_Wq_hi);
    cudaGetSymbolAddress((void**)&Wq_lo,  g_Wq_lo);
    cudaGetSymbolAddress((void**)&Wz_hi,  g_Wz_hi);
    cudaGetSymbolAddress((void**)&Wz_lo,  g_Wz_lo);
    cudaGetSymbolAddress((void**)&Wo_hi,  g_Wo_hi);
    cudaGetSymbolAddress((void**)&Wo_lo,  g_Wo_lo);
    cudaGetSymbolAddress((void**)&ab_hi,  g_ab_hi);
    cudaGetSymbolAddress((void**)&ab_lo,  g_ab_lo);
    cudaGetSymbolAddress((void**)&y_hi,   g_y_hi);
    cudaGetSymbolAddress((void**)&y_lo,   g_y_lo);

    const int smem128 = 3 * (2 * 16384 + 2 * 128 * 128);   // 196608
    const int smem32  = 3 * (2 * 16384 + 2 * 32 * 128);    // 122880
    cudaFuncSetAttribute(mma_gemm<128>, cudaFuncAttributeMaxDynamicSharedMemorySize, smem128);
    cudaFuncSetAttribute(mma_gemm<32>,  cudaFuncAttributeMaxDynamicSharedMemorySize, smem32);

    // operand prep
    cvt_hilo_kernel<<<(BT * Dc / 4 + 255) / 256, 256>>>(
        (const float4*)hs, (ushort4*)hsA_hi, (ushort4*)hsA_lo, BT * Dc / 4);
    transpose_cvt_kernel<<<dim3(CONVD / 32, Dc / 32), dim3(32, 8)>>>(W_qkv, Wq_hi, Wq_lo, Dc, CONVD);
    transpose_cvt_kernel<<<dim3(VALD / 32, Dc / 32), dim3(32, 8)>>>(W_z, Wz_hi, Wz_lo, Dc, VALD);
    transpose_cvt_kernel<<<dim3(Dc / 32, VALD / 32), dim3(32, 8)>>>(W_out, Wo_hi, Wo_lo, VALD, Dc);
    transpose_ab_kernel<<<dim3(Dc / 256, 32), 256>>>(W_a, W_b, ab_hi, ab_lo);

    // 1. mixed = hs @ W_qkv
    mma_gemm<128><<<dim3(CONVD / 128, BT / 128), 256, smem128>>>(
        hsA_hi, hsA_lo, Wq_hi, Wq_lo, mixed, BT, CONVD, Dc);
    // 2. depthwise causal conv + silu
    conv_silu_kernel<<<dim3(CONVD / 128, Tc / 256, Bc), 128>>>(mixed, conv_w, qkv);
    // 3. l2norm q, k
    l2norm_kernel<<<(2 * BT * Hc) / 8, 256>>>(qkv);
    // 4. a/b projection (N=32 GEMM) + activations
    mma_gemm<32><<<dim3(1, BT / 128), 256, smem32>>>(
        hsA_hi, hsA_lo, ab_hi, ab_lo, Cab, BT, 32, Dc);
    ab_act_kernel<<<(BT * Hc) / 256, 256>>>(Cab, dt_bias, A_log, gb);
    // 5. z = hs @ W_z
    mma_gemm<128><<<dim3(VALD / 128, BT / 128), 256, smem128>>>(
        hsA_hi, hsA_lo, Wz_hi, Wz_lo, z, BT, VALD, Dc);
    // 6. gated delta rule scan
    scan_kernel<<<Bc * Hc * 4, 256>>>(qkv, gb, od);
    // 7. gated RMSNorm -> y hi/lo
    gate_norm_kernel<<<(BT * Hc) / 8, 256>>>(od, z, norm_w, (ushort4*)y_hi, (ushort4*)y_lo);
    // 8. out = y @ W_out
    mma_gemm<128><<<dim3(Dc / 128, BT / 128), 256, smem128>>>(
        y_hi, y_lo, Wo_hi, Wo_lo, out, BT, Dc, Dc);
}

// round 6
// speedup vs baseline: 2.2614x; 1.6619x over previous
#include <cuda_runtime.h>
#include <cuda_fp16.h>
#include <cuda_bf16.h>
#include <cstdint>
#include <cstddef>

#define Bc    2
#define Tc    2048
#define Dc    2048
#define Hc    16
#define KEYD  2048
#define VALD  2048
#define CONVD 6144
#define BT    4096   // B*T

typedef unsigned short u16;
typedef uint32_t u32;

// ---------------- scratch (device globals: allocation-free) ----------------
__device__ float g_mixed[(size_t)BT * CONVD];   // qkv pre-conv (fp32)
__device__ float g_qkv[(size_t)BT * CONVD];     // post conv+silu (+l2norm in place)
__device__ float g_gb[2 * BT * Hc];             // g then beta
__device__ float g_z[(size_t)BT * VALD];
__device__ float g_od[(size_t)BT * VALD];       // delta-rule output
__device__ float g_Cab[(size_t)BT * 32];        // a/b projection pre-activation

// fp16 operands: A side split hi/lo (exact), B side single fp16
__device__ u16 g_hsA_hi[(size_t)BT * Dc];
__device__ u16 g_hsA_lo[(size_t)BT * Dc];
__device__ u16 g_Wq[(size_t)CONVD * Dc];
__device__ u16 g_Wz[(size_t)VALD * Dc];
__device__ u16 g_Wo[(size_t)Dc * VALD];
__device__ u16 g_ab[(size_t)32 * Dc];
__device__ u16 g_y_hi[(size_t)BT * VALD];
__device__ u16 g_y_lo[(size_t)BT * VALD];

// ---------------- helpers ----------------
__device__ __forceinline__ u16 h16bits(float x) {
    __half h = __float2half_rn(x);
    return *reinterpret_cast<u16*>(&h);
}
__device__ __forceinline__ float h16val(u16 u) {
    __half h;
    *reinterpret_cast<u16*>(&h) = u;
    return __half2float(h);
}
__device__ __forceinline__ u32 smem_u32(const void* p) {
    u32 a;
    asm("{ .reg .u64 t; cvta.to.shared.u64 t, %1; cvt.u32.u64 %0, t; }" : "=r"(a) : "l"(p));
    return a;
}
#define SWZ(x) ((x) ^ (((x) >> 3) & 0x70))

__device__ __forceinline__ void cp16(u32 s, const void* g) {
    asm volatile("cp.async.cg.shared.global [%0], [%1], 16;" :: "r"(s), "l"(g));
}
__device__ __forceinline__ void ldsm4(u32* r, u32 a) {
    asm volatile("ldmatrix.sync.aligned.m8n8.x4.shared.b16 {%0,%1,%2,%3}, [%4];"
                 : "=r"(r[0]), "=r"(r[1]), "=r"(r[2]), "=r"(r[3]) : "r"(a));
}
__device__ __forceinline__ void mma16816(float* c, const u32* a, const u32* b) {
    asm volatile(
        "mma.sync.aligned.m16n8k16.row.col.f32.f16.f16.f32 "
        "{%0,%1,%2,%3}, {%4,%5,%6,%7}, {%8,%9}, {%0,%1,%2,%3};"
        : "+f"(c[0]), "+f"(c[1]), "+f"(c[2]), "+f"(c[3])
        : "r"(a[0]), "r"(a[1]), "r"(a[2]), "r"(a[3]), "r"(b[0]), "r"(b[1]));
}

// ---------------- operand conversion kernels ----------------
__global__ void cvt_hilo_kernel(const float4* __restrict__ in,
                                ushort4* __restrict__ hi, ushort4* __restrict__ lo,
                                int n4) {
    int i = blockIdx.x * 256 + threadIdx.x;
    if (i >= n4) return;
    float4 v = in[i];
    ushort4 H, L;
    H.x = h16bits(v.x); L.x = h16bits(v.x - h16val(H.x));
    H.y = h16bits(v.y); L.y = h16bits(v.y - h16val(H.y));
    H.z = h16bits(v.z); L.z = h16bits(v.z - h16val(H.z));
    H.w = h16bits(v.w); L.w = h16bits(v.w - h16val(H.w));
    hi[i] = H; lo[i] = L;
}

// transpose + fp16 convert: W [Kd, N] fp32 -> T [N, Kd] fp16
__global__ void transpose_cvt_kernel(const float* __restrict__ W,
                                     u16* __restrict__ Th, int Kd, int N) {
    __shared__ float t[32][33];
    int n0 = blockIdx.x * 32, k0 = blockIdx.y * 32;
    int x = threadIdx.x, y = threadIdx.y;   // 32 x 8
#pragma unroll
    for (int i = 0; i < 4; ++i)
        t[y + 8 * i][x] = W[(size_t)(k0 + y + 8 * i) * N + n0 + x];
    __syncthreads();
#pragma unroll
    for (int i = 0; i < 4; ++i) {
        float v = t[x][y + 8 * i];
        Th[(size_t)(n0 + y + 8 * i) * Kd + k0 + x] = h16bits(v);
    }
}

// Wa,Wb [D,16] -> [32, D] fp16 (rows 0-15 = Wa^T, 16-31 = Wb^T)
__global__ void transpose_ab_kernel(const float* __restrict__ Wa,
                                    const float* __restrict__ Wb,
                                    u16* __restrict__ T) {
    int n = blockIdx.y;
    int k = blockIdx.x * 256 + threadIdx.x;
    const float* W = (n < 16) ? Wa : Wb;
    T[(size_t)n * Dc + k] = h16bits(W[(size_t)k * Hc + (n & 15)]);
}

// ---------------- HMMA GEMM: C[M,N] = A[M,K] @ Bt[N,K]^T ----------------
// A fp16 hi/lo (2 products, exact A), B single fp16; fp32 accumulate.
// 256 threads = 8 warps (4m x 2n). BK=64. 4-stage cp.async pipeline, 1 sync/iter.
template <int BN>
__global__ __launch_bounds__(256, 1)
void mma_gemm(const u16* __restrict__ Ahi, const u16* __restrict__ Alo,
              const u16* __restrict__ Bh, float* __restrict__ C,
              int M, int N, int Kd) {
    extern __shared__ __align__(1024) char smem[];
    constexpr int ATILE = 128 * 128;          // bytes per A half-tile
    constexpr int BTILE = BN * 128;
    constexpr int STAGE = 2 * ATILE + BTILE;
    constexpr int WN = BN / 2;                // warp n-tile
    constexpr int NG = WN / 16;               // ldmatrix.x4 groups per k16
    const int tid = threadIdx.x, lane = tid & 31, wid = tid >> 5;
    const int wm = (wid & 3) * 32;
    const int wn = (wid >> 2) * WN;
    const int m0 = blockIdx.y * 128, n0 = blockIdx.x * BN;
    const int ktiles = Kd >> 6;
    const u32 sb = smem_u32(smem);

    const u16* srcs[3] = {Ahi + (size_t)m0 * Kd, Alo + (size_t)m0 * Kd,
                          Bh + (size_t)n0 * Kd};
    const int rows[3] = {128, 128, BN};
    const u32 offs[3] = {0, ATILE, 2 * ATILE};

    auto issue = [&](int kt) {
        const int ko = kt << 6;
        const u32 st = sb + (u32)(kt & 3) * STAGE;
#pragma unroll
        for (int r = 0; r < 3; ++r) {
            for (int c = tid; c < rows[r] * 8; c += 256) {
                int rr = c >> 3, u = c & 7;
                cp16(st + offs[r] + SWZ(rr * 128 + u * 16),
                     srcs[r] + (size_t)rr * Kd + ko + u * 8);
            }
        }
    };

    float acc[2][WN / 8][4];
#pragma unroll
    for (int i = 0; i < 2; ++i)
#pragma unroll
        for (int j = 0; j < WN / 8; ++j)
#pragma unroll
            for (int l = 0; l < 4; ++l) acc[i][j][l] = 0.f;

    // prologue: stages 0..2
    issue(0);
    asm volatile("cp.async.commit_group;");
    issue(1);
    asm volatile("cp.async.commit_group;");
    issue(2);
    asm volatile("cp.async.commit_group;");

    for (int kt = 0; kt < ktiles; ++kt) {
        asm volatile("cp.async.wait_group 2;" ::: "memory");
        __syncthreads();
        if (kt + 3 < ktiles) issue(kt + 3);
        asm volatile("cp.async.commit_group;");

        const u32 Ab = sb + (u32)(kt & 3) * STAGE;
        const u32 Bb = Ab + 2 * ATILE;
#pragma unroll
        for (int ks = 0; ks < 4; ++ks) {
            u32 ah[2][4], al[2][4], bh[NG][4];
            const int arow = wm + (lane & 15);
            const int acol = ks * 32 + ((lane >> 4) << 4);
#pragma unroll
            for (int mf = 0; mf < 2; ++mf) {
                u32 ad = Ab + SWZ((arow + mf * 16) * 128 + acol);
                ldsm4(ah[mf], ad);
                ldsm4(al[mf], ad + ATILE);
            }
            const int brow = wn + (lane & 7) + ((lane >> 4) << 3);
            const int bcol = ks * 32 + ((lane & 8) << 1);
#pragma unroll
            for (int g = 0; g < NG; ++g)
                ldsm4(bh[g], Bb + SWZ((brow + g * 16) * 128 + bcol));
#pragma unroll
            for (int mf = 0; mf < 2; ++mf)
#pragma unroll
                for (int g = 0; g < NG; ++g) {
                    mma16816(acc[mf][2 * g + 0], ah[mf], &bh[g][0]);
                    mma16816(acc[mf][2 * g + 1], ah[mf], &bh[g][2]);
                    mma16816(acc[mf][2 * g + 0], al[mf], &bh[g][0]);
                    mma16816(acc[mf][2 * g + 1], al[mf], &bh[g][2]);
                }
        }
    }

    // epilogue: direct gmem stores
#pragma unroll
    for (int mf = 0; mf < 2; ++mf)
#pragma unroll
        for (int f = 0; f < WN / 8; ++f) {
            int row = m0 + wm + mf * 16 + (lane >> 2);
            int col = n0 + wn + f * 8 + (lane & 3) * 2;
            float2 lo2, hi2;
            lo2.x = acc[mf][f][0]; lo2.y = acc[mf][f][1];
            hi2.x = acc[mf][f][2]; hi2.y = acc[mf][f][3];
            *(float2*)&C[(size_t)row * N + col] = lo2;
            *(float2*)&C[(size_t)(row + 8) * N + col] = hi2;
        }
}

// ---------------- depthwise causal conv (K=4) + silu ----------------
__global__ void conv_silu_kernel(const float* __restrict__ mixed,
                                 const float* __restrict__ cw,
                                 float* __restrict__ out) {
    const int c  = blockIdx.x * 128 + threadIdx.x;
    const int b  = blockIdx.z;
    const int t0 = blockIdx.y * 256;
    const float w0 = cw[c * 4 + 0], w1 = cw[c * 4 + 1];
    const float w2 = cw[c * 4 + 2], w3 = cw[c * 4 + 3];
    const float* base  = mixed + (size_t)b * Tc * CONVD + c;
    float*       obase = out   + (size_t)b * Tc * CONVD + c;
    float xm3 = (t0 >= 3) ? base[(size_t)(t0 - 3) * CONVD] : 0.f;
    float xm2 = (t0 >= 2) ? base[(size_t)(t0 - 2) * CONVD] : 0.f;
    float xm1 = (t0 >= 1) ? base[(size_t)(t0 - 1) * CONVD] : 0.f;
    for (int t = t0; t < t0 + 256; ++t) {
        float x = base[(size_t)t * CONVD];
        float y = w0 * xm3 + w1 * xm2 + w2 * xm1 + w3 * x;
        float s = 1.f / (1.f + expf(-y));
        obase[(size_t)t * CONVD] = y * s;
        xm3 = xm2; xm2 = xm1; xm1 = x;
    }
}

// ---------------- per-head L2 norm for q and k (in place) ----------------
__global__ void l2norm_kernel(float* __restrict__ qkv) {
    const int warp = threadIdx.x >> 5, lane = threadIdx.x & 31;
    const int vec = blockIdx.x * 8 + warp;      // [0, 2*BT*H)
    const int qk = vec >> 16;                   // BT*H == 65536
    const int r  = vec & 65535;
    const int bt = r >> 4, h = r & 15;
    float* p = qkv + (size_t)bt * CONVD + qk * KEYD + h * 128 + lane * 4;
    float4 v = *(float4*)p;
    float ss = v.x * v.x + v.y * v.y + v.z * v.z + v.w * v.w;
#pragma unroll
    for (int off = 16; off; off >>= 1) ss += __shfl_xor_sync(~0u, ss, off);
    float scale = rsqrtf(ss + 1e-6f);
    if (qk == 0) scale *= 0.08838834764831845f;   // DK^-0.5
    v.x *= scale; v.y *= scale; v.z *= scale; v.w *= scale;
    *(float4*)p = v;
}

// ---------------- a/b activation ----------------
__global__ void ab_act_kernel(const float* __restrict__ Cab,
                              const float* __restrict__ dt_bias,
                              const float* __restrict__ A_log,
                              float* __restrict__ gb) {
    int i = blockIdx.x * 256 + threadIdx.x;     // over BT*16
    int m = i >> 4, h = i & 15;
    float av = Cab[(size_t)m * 32 + h];
    float bv = Cab[(size_t)m * 32 + 16 + h];
    float x = av + dt_bias[h];
    float sp = (x > 20.f) ? x : log1pf(expf(x));
    gb[i] = -expf(A_log[h]) * sp;
    gb[(size_t)BT * Hc + i] = 1.f / (1.f + expf(-bv));
}

// ---------------- gated delta rule scan (single merged reduction tree) ----------
__global__ __launch_bounds__(256, 1)
void scan_kernel(const float* __restrict__ qkv, const float* __restrict__ gb,
                 float* __restrict__ od) {
    const int blk  = blockIdx.x;
    const int vblk = blk & 3;
    const int h    = (blk >> 2) & 15;
    const int b    = blk >> 6;
    const int tid = threadIdx.x;
    const int tk = tid & 15, tv = tid >> 4;
    const int vbase = vblk * 32 + tv * 2;

    const float* qp = qkv + (size_t)b * Tc * CONVD + h * 128 + tk * 8;
    const float* kp = qp + KEYD;
    const float* vp = qkv + (size_t)b * Tc * CONVD + 2 * KEYD + h * 128 + vbase;
    const float* gp = gb + (size_t)b * Tc * Hc + h;
    const float* bp = gp + (size_t)BT * Hc;
    float* op = od + ((size_t)b * Tc * Hc + h) * 128 + vbase;

    float S[8][2];
#pragma unroll
    for (int i = 0; i < 8; ++i) { S[i][0] = 0.f; S[i][1] = 0.f; }

    for (int t = 0; t < Tc; ++t) {
        float4 q0 = *(const float4*)qp, q1 = *(const float4*)(qp + 4);
        float4 k0 = *(const float4*)kp, k1 = *(const float4*)(kp + 4);
        float2 vv = *(const float2*)vp;
        float gg = *gp, bb = *bp;
        float eg = __expf(gg);
        float kr[8] = {k0.x, k0.y, k0.z, k0.w, k1.x, k1.y, k1.z, k1.w};
        float qr[8] = {q0.x, q0.y, q0.z, q0.w, q1.x, q1.y, q1.z, q1.w};

        // all dot products against S_old + q.k, one reduction tree
        float ks0 = 0.f, ks1 = 0.f, qs0 = 0.f, qs1 = 0.f, qk = 0.f;
#pragma unroll
        for (int i = 0; i < 8; ++i) {
            ks0 = fmaf(kr[i], S[i][0], ks0);
            ks1 = fmaf(kr[i], S[i][1], ks1);
            qs0 = fmaf(qr[i], S[i][0], qs0);
            qs1 = fmaf(qr[i], S[i][1], qs1);
            qk  = fmaf(qr[i], kr[i], qk);
        }
#pragma unroll
        for (int off = 8; off; off >>= 1) {
            ks0 += __shfl_xor_sync(~0u, ks0, off);
            ks1 += __shfl_xor_sync(~0u, ks1, off);
            qs0 += __shfl_xor_sync(~0u, qs0, off);
            qs1 += __shfl_xor_sync(~0u, qs1, off);
            qk  += __shfl_xor_sync(~0u, qk, off);
        }
        float d0 = (vv.x - eg * ks0) * bb;
        float d1 = (vv.y - eg * ks1) * bb;
        if (tk == 0) {
            float2 ov;
            ov.x = fmaf(qk, d0, eg * qs0);
            ov.y = fmaf(qk, d1, eg * qs1);
            *(float2*)op = ov;
        }
#pragma unroll
        for (int i = 0; i < 8; ++i) {
            S[i][0] = fmaf(kr[i], d0, eg * S[i][0]);
            S[i][1] = fmaf(kr[i], d1, eg * S[i][1]);
        }
        qp += CONVD; kp += CONVD; vp += CONVD;
        gp += Hc; bp += Hc;
        op += (size_t)Hc * 128;
    }
}

// ---------------- gated RMSNorm -> fp16 hi/lo ----------------
__global__ void gate_norm_kernel(const float* __restrict__ od,
                                 const float* __restrict__ z,
                                 const float* __restrict__ nw,
                                 ushort4* __restrict__ yhi,
                                 ushort4* __restrict__ ylo) {
    const int warp = threadIdx.x >> 5, lane = threadIdx.x & 31;
    const int vec = blockIdx.x * 8 + warp;      // bt*H + h
    const float* opv = od + (size_t)vec * 128 + lane * 4;
    const float* zpv = z  + (size_t)vec * 128 + lane * 4;
    float4 o  = *(const float4*)opv;
    float4 zz = *(const float4*)zpv;
    float4 og;
    og.x = o.x * (zz.x / (1.f + expf(-zz.x)));
    og.y = o.y * (zz.y / (1.f + expf(-zz.y)));
    og.z = o.z * (zz.z / (1.f + expf(-zz.z)));
    og.w = o.w * (zz.w / (1.f + expf(-zz.w)));
    float ss = og.x * og.x + og.y * og.y + og.z * og.z + og.w * og.w;
#pragma unroll
    for (int off = 16; off; off >>= 1) ss += __shfl_xor_sync(~0u, ss, off);
    float r = rsqrtf(ss * (1.f / 128.f) + 1e-6f);
    float4 w = *(const float4*)&nw[lane * 4];
    float4 out;
    out.x = og.x * r * w.x; out.y = og.y * r * w.y;
    out.z = og.z * r * w.z; out.w = og.w * r * w.w;
    ushort4 H, L;
    H.x = h16bits(out.x); L.x = h16bits(out.x - h16val(H.x));
    H.y = h16bits(out.y); L.y = h16bits(out.y - h16val(H.y));
    H.z = h16bits(out.z); L.z = h16bits(out.z - h16val(H.z));
    H.w = h16bits(out.w); L.w = h16bits(out.w - h16val(H.w));
    yhi[(size_t)vec * 32 + lane] = H;
    ylo[(size_t)vec * 32 + lane] = L;
}

// ---------------- launch ----------------
extern "C" void kernel_launch(void* const* d_in, const int* in_sizes, int n_in,
                              void* d_out, int out_size) {
    const float* hs      = (const float*)d_in[0];
    const float* W_qkv   = (const float*)d_in[1];
    const float* conv_w  = (const float*)d_in[2];
    const float* W_z     = (const float*)d_in[3];
    const float* W_b     = (const float*)d_in[4];
    const float* W_a     = (const float*)d_in[5];
    const float* dt_bias = (const float*)d_in[6];
    const float* A_log   = (const float*)d_in[7];
    const float* norm_w  = (const float*)d_in[8];
    const float* W_out   = (const float*)d_in[9];
    float* out = (float*)d_out;

    float *mixed, *qkv, *gb, *z, *od, *Cab;
    u16 *hsA_hi, *hsA_lo, *Wq, *Wz, *Wo, *ab, *y_hi, *y_lo;
    cudaGetSymbolAddress((void**)&mixed, g_mixed);
    cudaGetSymbolAddress((void**)&qkv,   g_qkv);
    cudaGetSymbolAddress((void**)&gb,    g_gb);
    cudaGetSymbolAddress((void**)&z,     g_z);
    cudaGetSymbolAddress((void**)&od,    g_od);
    cudaGetSymbolAddress((void**)&Cab,   g_Cab);
    cudaGetSymbolAddress((void**)&hsA_hi, g_hsA_hi);
    cudaGetSymbolAddress((void**)&hsA_lo, g_hsA_lo);
    cudaGetSymbolAddress((void**)&Wq,  g_Wq);
    cudaGetSymbolAddress((void**)&Wz,  g_Wz);
    cudaGetSymbolAddress((void**)&Wo,  g_Wo);
    cudaGetSymbolAddress((void**)&ab,  g_ab);
    cudaGetSymbolAddress((void**)&y_hi, g_y_hi);
    cudaGetSymbolAddress((void**)&y_lo, g_y_lo);

    const int smem128 = 4 * (2 * 16384 + 128 * 128);   // 196608
    const int smem32  = 4 * (2 * 16384 + 32 * 128);    // 147456
    cudaFuncSetAttribute(mma_gemm<128>, cudaFuncAttributeMaxDynamicSharedMemorySize, smem128);
    cudaFuncSetAttribute(mma_gemm<32>,  cudaFuncAttributeMaxDynamicSharedMemorySize, smem32);

    // operand prep
    cvt_hilo_kernel<<<(BT * Dc / 4 + 255) / 256, 256>>>(
        (const float4*)hs, (ushort4*)hsA_hi, (ushort4*)hsA_lo, BT * Dc / 4);
    transpose_cvt_kernel<<<dim3(CONVD / 32, Dc / 32), dim3(32, 8)>>>(W_qkv, Wq, Dc, CONVD);
    transpose_cvt_kernel<<<dim3(VALD / 32, Dc / 32), dim3(32, 8)>>>(W_z, Wz, Dc, VALD);
    transpose_cvt_kernel<<<dim3(Dc / 32, VALD / 32), dim3(32, 8)>>>(W_out, Wo, VALD, Dc);
    transpose_ab_kernel<<<dim3(Dc / 256, 32), 256>>>(W_a, W_b, ab);

    // 1. mixed = hs @ W_qkv
    mma_gemm<128><<<dim3(CONVD / 128, BT / 128), 256, smem128>>>(
        hsA_hi, hsA_lo, Wq, mixed, BT, CONVD, Dc);
    // 2. depthwise causal conv + silu
    conv_silu_kernel<<<dim3(CONVD / 128, Tc / 256, Bc), 128>>>(mixed, conv_w, qkv);
    // 3. l2norm q, k
    l2norm_kernel<<<(2 * BT * Hc) / 8, 256>>>(qkv);
    // 4. a/b projection (N=32 GEMM) + activations
    mma_gemm<32><<<dim3(1, BT / 128), 256, smem32>>>(
        hsA_hi, hsA_lo, ab, Cab, BT, 32, Dc);
    ab_act_kernel<<<(BT * Hc) / 256, 256>>>(Cab, dt_bias, A_log, gb);
    // 5. z = hs @ W_z
    mma_gemm<128><<<dim3(VALD / 128, BT / 128), 256, smem128>>>(
        hsA_hi, hsA_lo, Wz, z, BT, VALD, Dc);
    // 6. gated delta rule scan
    scan_kernel<<<Bc * Hc * 4, 256>>>(qkv, gb, od);
    // 7. gated RMSNorm -> y hi/lo
    gate_norm_kernel<<<(BT * Hc) / 8, 256>>>(od, z, norm_w, (ushort4*)y_hi, (ushort4*)y_lo);
    // 8. out = y @ W_out
    mma_gemm<128><<<dim3(Dc / 128, BT / 128), 256, smem128>>>(
        y_hi, y_lo, Wo, out, BT, Dc, Dc);
}